// round 15
// baseline (speedup 1.0000x reference)
#include <cuda_runtime.h>
#include <cstdint>

// Shapes
#define Bq 8
#define Sq 8192
#define Nq 16
#define NCH 2                     // s-chunks (CTAs per bn)
#define SSUB (Sq / NCH)           // 4096
#define ST 32                     // s-rows per tile
#define NT2 (SSUB / ST)           // 128 tiles per CTA
#define RSTRIDE 272               // smem row stride bytes (136 bf16)
#define TILE_B (ST * RSTRIDE)     // 8704
#define BUF_B (2 * TILE_B)        // 17408 = V tile + K tile
#define V_ELEMS 8192
#define SST_ELEMS 524288

// Deterministic reduction scratch + arrival counters
__device__ float g_part[128 * NCH * 4096];   // 4 MB
__device__ float g_zp[128 * NCH * 64];
__device__ int   g_cnt[128];                 // zero-init; reset after each use

static __device__ __forceinline__ float elu1(float x) {
    return x > 0.0f ? x + 1.0f : __expf(x);
}
static __device__ __forceinline__ uint32_t smem_u32(const void* p) {
    uint32_t a;
    asm("{ .reg .u64 t; cvta.to.shared.u64 t, %1; cvt.u32.u64 %0, t; }" : "=r"(a) : "l"(p));
    return a;
}
static __device__ __forceinline__ uint32_t pk(float hi, float lo) {
    uint32_t r;
    asm("cvt.rn.bf16x2.f32 %0, %1, %2;" : "=r"(r) : "f"(hi), "f"(lo));
    return r;
}
static __device__ __forceinline__ float bf_lo(uint32_t p) {
    return __uint_as_float(p << 16);
}
static __device__ __forceinline__ float bf_up(uint32_t p) {
    return __uint_as_float(p & 0xFFFF0000u);
}
static __device__ __forceinline__ void ldsm4t(uint32_t* r, uint32_t a) {
    asm volatile("ldmatrix.sync.aligned.m8n8.x4.trans.shared.b16 {%0,%1,%2,%3}, [%4];"
                 : "=r"(r[0]), "=r"(r[1]), "=r"(r[2]), "=r"(r[3]) : "r"(a));
}
static __device__ __forceinline__ void mma16816(float* c, const uint32_t* a,
                                                uint32_t b0, uint32_t b1) {
    asm volatile(
        "mma.sync.aligned.m16n8k16.row.col.f32.bf16.bf16.f32 "
        "{%0,%1,%2,%3}, {%4,%5,%6,%7}, {%8,%9}, {%0,%1,%2,%3};"
        : "+f"(c[0]), "+f"(c[1]), "+f"(c[2]), "+f"(c[3])
        : "r"(a[0]), "r"(a[1]), "r"(a[2]), "r"(a[3]), "r"(b0), "r"(b1));
}
static __device__ __forceinline__ void sts128(uint32_t a, uint32_t x, uint32_t y,
                                              uint32_t z, uint32_t w) {
    asm volatile("st.shared.v4.b32 [%0], {%1,%2,%3,%4};"
                 :: "r"(a), "r"(x), "r"(y), "r"(z), "r"(w) : "memory");
}

// ---------------------------------------------------------------------------
// Fused: per (bn, chunk) partial Sst + Z; last-arriving CTA of each bn
// performs the deterministic 2-way reduction + epilogue.
// Pipeline order per tile: compute k0 | stage next | LDG next+1 | compute k1 | BAR
// ---------------------------------------------------------------------------
__global__ void __launch_bounds__(256, 2) rcla_hmma(
    const float* __restrict__ query,   // [B,N,64]
    const float* __restrict__ key,     // [B,S,N,64]
    const float* __restrict__ value,   // [B,S,N,64]
    const int*   __restrict__ kmask,   // [B,S] nonzero = masked
    float* __restrict__ outV,          // [B,N,64]
    float* __restrict__ outS,          // [B,N,64,64]
    float* __restrict__ outZ)          // [B,N,64]
{
    __shared__ __align__(16) unsigned char s_tiles[2 * BUF_B];  // 34816 B
    __shared__ float s_z[ST][64];                               // 8 KB
    __shared__ float s_qs[64];
    __shared__ float s_red[64];
    __shared__ float s_sinv;
    __shared__ int s_rank;

    const int tid = threadIdx.x;
    const int wid = tid >> 5;
    const int lid = tid & 31;
    const int bn = blockIdx.x;
    const int ch = blockIdx.y;
    const int b = bn >> 4;
    const int n = bn & 15;

    const uint32_t sb = smem_u32(s_tiles);

    // ---- staging mapping ----
    const int s_loc = tid >> 3;            // 0..31
    const int dgrp = (tid & 7) * 8;        // 0..56
    const uint32_t st_off = (uint32_t)s_loc * RSTRIDE + dgrp * 2;

    const int sbase = ch * SSUB + s_loc;
    const float* kg = key   + (((size_t)b * Sq + sbase) * Nq + n) * 64 + dgrp;
    const float* vg = value + (((size_t)b * Sq + sbase) * Nq + n) * 64 + dgrp;
    const int*   mg = kmask + b * Sq + sbase;
    const size_t GSTR = (size_t)ST * Nq * 64;

    // ---- mma mapping ----
    const bool isC1 = wid < 4;
    const int mbase = isC1 ? ((wid & 2) ? 64 : 0) : 0;          // A rows
    const int dsm   = isC1 ? ((wid & 1) * 32) : (64 + (wid & 3) * 16);  // B smem col
    const int dout  = isC1 ? ((wid & 1) * 32) : ((wid & 3) * 16);       // output d
    const int g = lid >> 2;
    const int tig = lid & 3;

    const uint32_t offA = (uint32_t)((lid & 7) + ((lid & 16) ? 8 : 0)) * RSTRIDE
                        + (uint32_t)(mbase + ((lid & 8) ? 8 : 0)) * 2;
    const uint32_t offB = (uint32_t)((lid & 7) + ((lid & 8) ? 8 : 0)) * RSTRIDE
                        + (uint32_t)(dsm + ((lid & 16) ? 8 : 0)) * 2;

    float c[4][4][4];
#pragma unroll
    for (int i = 0; i < 4; i++)
#pragma unroll
        for (int j = 0; j < 4; j++)
#pragma unroll
            for (int r = 0; r < 4; r++) c[i][j][r] = 0.0f;
    float zacc[8];
#pragma unroll
    for (int j = 0; j < 8; j++) zacc[j] = 0.0f;

    // staging of regs -> smem tile (K: mask+elu+split+z; V: split)
#define STAGE_TILE(VT, KT)                                                     \
    {                                                                          \
        const float mm = mk ? 0.0f : 1.0f;                                     \
        float f0 = mm * elu1(k0.x), f1 = mm * elu1(k0.y);                      \
        float f2 = mm * elu1(k0.z), f3 = mm * elu1(k0.w);                      \
        float f4 = mm * elu1(k1.x), f5 = mm * elu1(k1.y);                      \
        float f6 = mm * elu1(k1.z), f7 = mm * elu1(k1.w);                      \
        zacc[0] += f0; zacc[1] += f1; zacc[2] += f2; zacc[3] += f3;            \
        zacc[4] += f4; zacc[5] += f5; zacc[6] += f6; zacc[7] += f7;            \
        const uint32_t h01 = pk(f1, f0), h23 = pk(f3, f2);                     \
        const uint32_t h45 = pk(f5, f4), h67 = pk(f7, f6);                     \
        sts128((KT) + st_off, h01, h23, h45, h67);                             \
        const uint32_t l01 = pk(f1 - bf_up(h01), f0 - bf_lo(h01));             \
        const uint32_t l23 = pk(f3 - bf_up(h23), f2 - bf_lo(h23));             \
        const uint32_t l45 = pk(f5 - bf_up(h45), f4 - bf_lo(h45));             \
        const uint32_t l67 = pk(f7 - bf_up(h67), f6 - bf_lo(h67));             \
        sts128((KT) + st_off + 128, l01, l23, l45, l67);                       \
        const float g0 = v0.x, g1 = v0.y, g2 = v0.z, g3 = v0.w;                \
        const float g4 = v1.x, g5 = v1.y, g6 = v1.z, g7 = v1.w;                \
        const uint32_t j01 = pk(g1, g0), j23 = pk(g3, g2);                     \
        const uint32_t j45 = pk(g5, g4), j67 = pk(g7, g6);                     \
        sts128((VT) + st_off, j01, j23, j45, j67);                             \
        const uint32_t m01 = pk(g1 - bf_up(j01), g0 - bf_lo(j01));             \
        const uint32_t m23 = pk(g3 - bf_up(j23), g2 - bf_lo(j23));             \
        const uint32_t m45 = pk(g5 - bf_up(j45), g4 - bf_lo(j45));             \
        const uint32_t m67 = pk(g7 - bf_up(j67), g6 - bf_lo(j67));             \
        sts128((VT) + st_off + 128, m01, m23, m45, m67);                       \
    }

#define COMPUTE_KSTEP(VT, KT, KS)                                              \
    {                                                                          \
        const uint32_t rowoff = (uint32_t)(KS) * 16 * RSTRIDE;                 \
        uint32_t a[4][4];                                                      \
        _Pragma("unroll")                                                      \
        for (int ai = 0; ai < 4; ai++)                                         \
            ldsm4t(a[ai], (VT) + rowoff + offA + ai * 32);                     \
        if (isC1) {                                                            \
            uint32_t bb[2][4];                                                 \
            _Pragma("unroll")                                                  \
            for (int bj = 0; bj < 2; bj++)                                     \
                ldsm4t(bb[bj], (KT) + rowoff + offB + bj * 32);                \
            _Pragma("unroll")                                                  \
            for (int ai = 0; ai < 4; ai++)                                     \
                _Pragma("unroll")                                              \
                for (int nb = 0; nb < 4; nb++)                                 \
                    mma16816(c[ai][nb], a[ai],                                 \
                             bb[nb >> 1][(nb & 1) * 2],                        \
                             bb[nb >> 1][(nb & 1) * 2 + 1]);                   \
        } else {                                                               \
            uint32_t bb[4];                                                    \
            ldsm4t(bb, (KT) + rowoff + offB);                                  \
            _Pragma("unroll")                                                  \
            for (int ai = 0; ai < 4; ai++) {                                   \
                mma16816(c[ai][0], a[ai], bb[0], bb[1]);                       \
                mma16816(c[ai][1], a[ai], bb[2], bb[3]);                       \
            }                                                                  \
        }                                                                      \
    }

    // ---- prologue: load+stage tile 0, load tile 1 ----
    float4 k0 = *(const float4*)kg;
    float4 k1 = *(const float4*)(kg + 4);
    float4 v0 = *(const float4*)vg;
    float4 v1 = *(const float4*)(vg + 4);
    int mk = *mg;
    STAGE_TILE(sb, sb + TILE_B);
    kg += GSTR; vg += GSTR; mg += ST;
    k0 = *(const float4*)kg;
    k1 = *(const float4*)(kg + 4);
    v0 = *(const float4*)vg;
    v1 = *(const float4*)(vg + 4);
    mk = *mg;
    __syncthreads();

    for (int it = 0; it < NT2; it++) {
        const uint32_t vt = sb + (it & 1) * BUF_B;
        const uint32_t kt = vt + TILE_B;
        const uint32_t vtn = sb + ((it + 1) & 1) * BUF_B;
        const uint32_t ktn = vtn + TILE_B;

        COMPUTE_KSTEP(vt, kt, 0);

        if (it + 1 < NT2) STAGE_TILE(vtn, ktn);   // regs hold tile it+1

        if (it + 2 < NT2) {
            kg += GSTR; vg += GSTR; mg += ST;
            k0 = *(const float4*)kg;
            k1 = *(const float4*)(kg + 4);
            v0 = *(const float4*)vg;
            v1 = *(const float4*)(vg + 4);
            mk = *mg;
        }

        COMPUTE_KSTEP(vt, kt, 1);

        __syncthreads();
    }

    // ---- partial Z ----
#pragma unroll
    for (int j = 0; j < 8; j++) s_z[s_loc][dgrp + j] = zacc[j];
    __syncthreads();
    if (tid < 64) {
        float z = 0.0f;
#pragma unroll
        for (int p = 0; p < ST; p++) z += s_z[p][tid];
        g_zp[(bn * NCH + ch) * 64 + tid] = z;
    }

    // ---- fold: Sst[m][d] = C1[m][d] (w0,1) + C1[m+64][d] (w2,3) + C2[m][d] (w4-7)
    float* fold = (float*)s_tiles;   // 64 rows x 66 stride

    if (wid == 2 || wid == 3) {
#pragma unroll
        for (int ai = 0; ai < 4; ai++)
#pragma unroll
            for (int nb = 0; nb < 4; nb++) {
                const int m = ai * 16 + g;
                const int d0 = dout + nb * 8 + 2 * tig;
                fold[m * 66 + d0]           = c[ai][nb][0];
                fold[m * 66 + d0 + 1]       = c[ai][nb][1];
                fold[(m + 8) * 66 + d0]     = c[ai][nb][2];
                fold[(m + 8) * 66 + d0 + 1] = c[ai][nb][3];
            }
    }
    __syncthreads();
    if (wid < 2) {
#pragma unroll
        for (int ai = 0; ai < 4; ai++)
#pragma unroll
            for (int nb = 0; nb < 4; nb++) {
                const int m = ai * 16 + g;
                const int d0 = dout + nb * 8 + 2 * tig;
                c[ai][nb][0] += fold[m * 66 + d0];
                c[ai][nb][1] += fold[m * 66 + d0 + 1];
                c[ai][nb][2] += fold[(m + 8) * 66 + d0];
                c[ai][nb][3] += fold[(m + 8) * 66 + d0 + 1];
            }
    }
    __syncthreads();
    if (wid >= 4) {
#pragma unroll
        for (int ai = 0; ai < 4; ai++)
#pragma unroll
            for (int nb = 0; nb < 2; nb++) {
                const int m = ai * 16 + g;
                const int d0 = dout + nb * 8 + 2 * tig;
                fold[m * 66 + d0]           = c[ai][nb][0];
                fold[m * 66 + d0 + 1]       = c[ai][nb][1];
                fold[(m + 8) * 66 + d0]     = c[ai][nb][2];
                fold[(m + 8) * 66 + d0 + 1] = c[ai][nb][3];
            }
    }
    __syncthreads();

    if (wid < 2) {
        float* so = g_part + ((size_t)bn * NCH + ch) * 4096;
#pragma unroll
        for (int ai = 0; ai < 4; ai++)
#pragma unroll
            for (int nb = 0; nb < 4; nb++) {
                const int m = ai * 16 + g;
                const int d0 = dout + nb * 8 + 2 * tig;
                float c0 = c[ai][nb][0] + fold[m * 66 + d0];
                float c1 = c[ai][nb][1] + fold[m * 66 + d0 + 1];
                float c2 = c[ai][nb][2] + fold[(m + 8) * 66 + d0];
                float c3 = c[ai][nb][3] + fold[(m + 8) * 66 + d0 + 1];
                *(float2*)(so + m * 64 + d0)       = make_float2(c0, c1);
                *(float2*)(so + (m + 8) * 64 + d0) = make_float2(c2, c3);
            }
    }

    // ---- arrival protocol: second CTA of this bn does the reduction ----
    __threadfence();
    __syncthreads();
    if (tid == 0) s_rank = atomicAdd(&g_cnt[bn], 1);
    __syncthreads();

    if (s_rank == 1) {
        __threadfence();   // acquire: other CTA's partials visible
        float* sst = (float*)s_tiles;   // reuse as 4096-float buffer

        const float* p0 = g_part + (size_t)bn * (NCH * 4096);
        for (int e = tid; e < 4096; e += 256) {
            const float s = p0[e] + p0[4096 + e];
            sst[e] = s;
            outS[(size_t)bn * 4096 + e] = s;
        }
        if (tid < 64) {
            const float z = g_zp[bn * 128 + tid] + g_zp[bn * 128 + 64 + tid];
            outZ[bn * 64 + tid] = z;
            const float q = elu1(query[bn * 64 + tid]);
            s_qs[tid] = q;
            s_red[tid] = q * z;
        }
        __syncthreads();
        if (tid == 0) {
            float s = 0.0f;
#pragma unroll
            for (int d = 0; d < 64; d++) s += s_red[d];
            s_sinv = 1.0f / (s + 1e-6f);
            g_cnt[bn] = 0;   // reset for next graph replay
        }
        __syncthreads();
        {
            const int m = tid >> 2;       // 0..63
            const int l4 = tid & 3;
            float v = 0.0f;
#pragma unroll
            for (int u = 0; u < 16; u++) {
                const int d = l4 * 16 + u;
                v += s_qs[d] * sst[m * 64 + d];
            }
            v += __shfl_xor_sync(0xFFFFFFFFu, v, 1);
            v += __shfl_xor_sync(0xFFFFFFFFu, v, 2);
            if (l4 == 0) outV[bn * 64 + m] = v * s_sinv;
        }
    }
}

// ---------------------------------------------------------------------------
extern "C" void kernel_launch(void* const* d_in, const int* in_sizes, int n_in,
                              void* d_out, int out_size)
{
    const float* query = (const float*)d_in[0];
    const float* key   = (const float*)d_in[1];
    const float* value = (const float*)d_in[2];
    const int*   mask  = (const int*)d_in[3];

    float* out  = (float*)d_out;
    float* outV = out;                        // [B,N,M]
    float* outS = out + V_ELEMS;              // [B,N,M,D]
    float* outZ = out + V_ELEMS + SST_ELEMS;  // [B,N,D]

    rcla_hmma<<<dim3(128, NCH), 256>>>(query, key, value, mask,
                                       outV, outS, outZ);
}

// round 16
// speedup vs baseline: 1.0696x; 1.0696x over previous
#include <cuda_runtime.h>
#include <cstdint>

// Shapes
#define Bq 8
#define Sq 8192
#define Nq 16
#define NCH 2                     // s-chunks (CTAs per bn)
#define SSUB (Sq / NCH)           // 4096
#define ST 64                     // s-rows per tile (2 batches of 32)
#define NT2 (SSUB / ST)           // 64 tiles per CTA
#define RSTRIDE 272               // smem row stride bytes (136 bf16)
#define TILE_B (ST * RSTRIDE)     // 17408
#define BUF_B (2 * TILE_B)        // 34816 = V tile + K tile
#define DYN_B (2 * BUF_B)         // 69632 dynamic smem
#define V_ELEMS 8192
#define SST_ELEMS 524288

// Deterministic reduction scratch + arrival counters
__device__ float g_part[128 * NCH * 4096];   // 4 MB
__device__ float g_zp[128 * NCH * 64];
__device__ int   g_cnt[128];                 // zero-init; reset after each use

static __device__ __forceinline__ float elu1(float x) {
    return x > 0.0f ? x + 1.0f : __expf(x);
}
static __device__ __forceinline__ uint32_t smem_u32(const void* p) {
    uint32_t a;
    asm("{ .reg .u64 t; cvta.to.shared.u64 t, %1; cvt.u32.u64 %0, t; }" : "=r"(a) : "l"(p));
    return a;
}
static __device__ __forceinline__ uint32_t pk(float hi, float lo) {
    uint32_t r;
    asm("cvt.rn.bf16x2.f32 %0, %1, %2;" : "=r"(r) : "f"(hi), "f"(lo));
    return r;
}
static __device__ __forceinline__ float bf_lo(uint32_t p) {
    return __uint_as_float(p << 16);
}
static __device__ __forceinline__ float bf_up(uint32_t p) {
    return __uint_as_float(p & 0xFFFF0000u);
}
static __device__ __forceinline__ void ldsm4t(uint32_t* r, uint32_t a) {
    asm volatile("ldmatrix.sync.aligned.m8n8.x4.trans.shared.b16 {%0,%1,%2,%3}, [%4];"
                 : "=r"(r[0]), "=r"(r[1]), "=r"(r[2]), "=r"(r[3]) : "r"(a));
}
static __device__ __forceinline__ void mma16816(float* c, const uint32_t* a,
                                                uint32_t b0, uint32_t b1) {
    asm volatile(
        "mma.sync.aligned.m16n8k16.row.col.f32.bf16.bf16.f32 "
        "{%0,%1,%2,%3}, {%4,%5,%6,%7}, {%8,%9}, {%0,%1,%2,%3};"
        : "+f"(c[0]), "+f"(c[1]), "+f"(c[2]), "+f"(c[3])
        : "r"(a[0]), "r"(a[1]), "r"(a[2]), "r"(a[3]), "r"(b0), "r"(b1));
}
static __device__ __forceinline__ void sts128(uint32_t a, uint32_t x, uint32_t y,
                                              uint32_t z, uint32_t w) {
    asm volatile("st.shared.v4.b32 [%0], {%1,%2,%3,%4};"
                 :: "r"(a), "r"(x), "r"(y), "r"(z), "r"(w) : "memory");
}

// ---------------------------------------------------------------------------
// Fused: per (bn, chunk) partial Sst + Z; last-arriving CTA of each bn
// performs the deterministic 2-way reduction + epilogue.
// ST=64 tiles: one barrier per 64 s-rows; batch A prefetched (17 regs, as
// R14), batch B loaded inline in the stage phase (no cross-compute liveness).
// ---------------------------------------------------------------------------
__global__ void __launch_bounds__(256, 2) rcla_hmma(
    const float* __restrict__ query,   // [B,N,64]
    const float* __restrict__ key,     // [B,S,N,64]
    const float* __restrict__ value,   // [B,S,N,64]
    const int*   __restrict__ kmask,   // [B,S] nonzero = masked
    float* __restrict__ outV,          // [B,N,64]
    float* __restrict__ outS,          // [B,N,64,64]
    float* __restrict__ outZ)          // [B,N,64]
{
    extern __shared__ __align__(16) unsigned char s_tiles[];    // DYN_B
    __shared__ float s_z[32][64];                               // 8 KB
    __shared__ float s_qs[64];
    __shared__ float s_red[64];
    __shared__ float s_sinv;
    __shared__ int s_rank;

    const int tid = threadIdx.x;
    const int wid = tid >> 5;
    const int lid = tid & 31;
    const int bn = blockIdx.x;
    const int ch = blockIdx.y;
    const int b = bn >> 4;
    const int n = bn & 15;

    const uint32_t sb = smem_u32(s_tiles);

    // ---- staging mapping ----
    const int s_loc = tid >> 3;            // 0..31 (batch A row; batch B = +32)
    const int dgrp = (tid & 7) * 8;        // 0..56
    const uint32_t st_off = (uint32_t)s_loc * RSTRIDE + dgrp * 2;

    const int sbase = ch * SSUB + s_loc;
    const float* kg = key   + (((size_t)b * Sq + sbase) * Nq + n) * 64 + dgrp;
    const float* vg = value + (((size_t)b * Sq + sbase) * Nq + n) * 64 + dgrp;
    const int*   mg = kmask + b * Sq + sbase;
    const size_t GSTR = (size_t)ST * Nq * 64;     // floats per tile
    const size_t HSTR = (size_t)32 * Nq * 64;     // batch B offset (32 s-rows)

    // ---- mma mapping ----
    const bool isC1 = wid < 4;
    const int mbase = isC1 ? ((wid & 2) ? 64 : 0) : 0;          // A rows
    const int dsm   = isC1 ? ((wid & 1) * 32) : (64 + (wid & 3) * 16);  // B smem col
    const int dout  = isC1 ? ((wid & 1) * 32) : ((wid & 3) * 16);       // output d
    const int g = lid >> 2;
    const int tig = lid & 3;

    const uint32_t offA = (uint32_t)((lid & 7) + ((lid & 16) ? 8 : 0)) * RSTRIDE
                        + (uint32_t)(mbase + ((lid & 8) ? 8 : 0)) * 2;
    const uint32_t offB = (uint32_t)((lid & 7) + ((lid & 8) ? 8 : 0)) * RSTRIDE
                        + (uint32_t)(dsm + ((lid & 16) ? 8 : 0)) * 2;

    float c[4][4][4];
#pragma unroll
    for (int i = 0; i < 4; i++)
#pragma unroll
        for (int j = 0; j < 4; j++)
#pragma unroll
            for (int r = 0; r < 4; r++) c[i][j][r] = 0.0f;
    float zacc[8];
#pragma unroll
    for (int j = 0; j < 8; j++) zacc[j] = 0.0f;

// stage one 32-row batch from the named regs into (VT,KT) at row offset ROFF
#define STAGE_B(VT, KT, ROFF, K0, K1, V0, V1, MK)                              \
    {                                                                          \
        const float mm = (MK) ? 0.0f : 1.0f;                                   \
        float f0 = mm * elu1((K0).x), f1 = mm * elu1((K0).y);                  \
        float f2 = mm * elu1((K0).z), f3 = mm * elu1((K0).w);                  \
        float f4 = mm * elu1((K1).x), f5 = mm * elu1((K1).y);                  \
        float f6 = mm * elu1((K1).z), f7 = mm * elu1((K1).w);                  \
        zacc[0] += f0; zacc[1] += f1; zacc[2] += f2; zacc[3] += f3;            \
        zacc[4] += f4; zacc[5] += f5; zacc[6] += f6; zacc[7] += f7;            \
        const uint32_t h01 = pk(f1, f0), h23 = pk(f3, f2);                     \
        const uint32_t h45 = pk(f5, f4), h67 = pk(f7, f6);                     \
        sts128((KT) + st_off + (ROFF), h01, h23, h45, h67);                    \
        const uint32_t l01 = pk(f1 - bf_up(h01), f0 - bf_lo(h01));             \
        const uint32_t l23 = pk(f3 - bf_up(h23), f2 - bf_lo(h23));             \
        const uint32_t l45 = pk(f5 - bf_up(h45), f4 - bf_lo(h45));             \
        const uint32_t l67 = pk(f7 - bf_up(h67), f6 - bf_lo(h67));             \
        sts128((KT) + st_off + (ROFF) + 128, l01, l23, l45, l67);              \
        const float g0 = (V0).x, g1 = (V0).y, g2 = (V0).z, g3 = (V0).w;        \
        const float g4 = (V1).x, g5 = (V1).y, g6 = (V1).z, g7 = (V1).w;        \
        const uint32_t j01 = pk(g1, g0), j23 = pk(g3, g2);                     \
        const uint32_t j45 = pk(g5, g4), j67 = pk(g7, g6);                     \
        sts128((VT) + st_off + (ROFF), j01, j23, j45, j67);                    \
        const uint32_t m01 = pk(g1 - bf_up(j01), g0 - bf_lo(j01));             \
        const uint32_t m23 = pk(g3 - bf_up(j23), g2 - bf_lo(j23));             \
        const uint32_t m45 = pk(g5 - bf_up(j45), g4 - bf_lo(j45));             \
        const uint32_t m67 = pk(g7 - bf_up(j67), g6 - bf_lo(j67));             \
        sts128((VT) + st_off + (ROFF) + 128, m01, m23, m45, m67);              \
    }

#define COMPUTE_KSTEP(VT, KT, KS)                                              \
    {                                                                          \
        const uint32_t rowoff = (uint32_t)(KS) * 16 * RSTRIDE;                 \
        uint32_t a[4][4];                                                      \
        _Pragma("unroll")                                                      \
        for (int ai = 0; ai < 4; ai++)                                         \
            ldsm4t(a[ai], (VT) + rowoff + offA + ai * 32);                     \
        if (isC1) {                                                            \
            uint32_t bb[2][4];                                                 \
            _Pragma("unroll")                                                  \
            for (int bj = 0; bj < 2; bj++)                                     \
                ldsm4t(bb[bj], (KT) + rowoff + offB + bj * 32);                \
            _Pragma("unroll")                                                  \
            for (int ai = 0; ai < 4; ai++)                                     \
                _Pragma("unroll")                                              \
                for (int nb = 0; nb < 4; nb++)                                 \
                    mma16816(c[ai][nb], a[ai],                                 \
                             bb[nb >> 1][(nb & 1) * 2],                        \
                             bb[nb >> 1][(nb & 1) * 2 + 1]);                   \
        } else {                                                               \
            uint32_t bb[4];                                                    \
            ldsm4t(bb, (KT) + rowoff + offB);                                  \
            _Pragma("unroll")                                                  \
            for (int ai = 0; ai < 4; ai++) {                                   \
                mma16816(c[ai][0], a[ai], bb[0], bb[1]);                       \
                mma16816(c[ai][1], a[ai], bb[2], bb[3]);                       \
            }                                                                  \
        }                                                                      \
    }

    // ---- prologue: prefetch batch A of tile 0 ----
    float4 k0 = *(const float4*)kg;
    float4 k1 = *(const float4*)(kg + 4);
    float4 v0 = *(const float4*)vg;
    float4 v1 = *(const float4*)(vg + 4);
    int mk = *mg;

    for (int it = 0; it < NT2; it++) {
        const uint32_t vt = sb + (it & 1) * BUF_B;
        const uint32_t kt = vt + TILE_B;

        // ---- batch B loads issued first (latency covered by batch A work) ----
        const float4 kb0 = *(const float4*)(kg + HSTR);
        const float4 kb1 = *(const float4*)(kg + HSTR + 4);
        const float4 vb0 = *(const float4*)(vg + HSTR);
        const float4 vb1 = *(const float4*)(vg + HSTR + 4);
        const int mkb = mg[32];

        // ---- stage batch A (rows s_loc) from prefetch regs ----
        STAGE_B(vt, kt, 0, k0, k1, v0, v1, mk);
        // ---- stage batch B (rows s_loc+32) ----
        STAGE_B(vt, kt, 32u * RSTRIDE, kb0, kb1, vb0, vb1, mkb);

        // ---- prefetch batch A of next tile ----
        if (it + 1 < NT2) {
            kg += GSTR; vg += GSTR; mg += ST;
            k0 = *(const float4*)kg;
            k1 = *(const float4*)(kg + 4);
            v0 = *(const float4*)vg;
            v1 = *(const float4*)(vg + 4);
            mk = *mg;
        }

        __syncthreads();   // stage visible; also fences reads of this buf @ it-2

        // ---- compute: 4 k-steps of 16 ----
        COMPUTE_KSTEP(vt, kt, 0);
        COMPUTE_KSTEP(vt, kt, 1);
        COMPUTE_KSTEP(vt, kt, 2);
        COMPUTE_KSTEP(vt, kt, 3);
        // no trailing sync: next iteration writes the other buffer
    }

    // ---- partial Z ----
#pragma unroll
    for (int j = 0; j < 8; j++) s_z[s_loc][dgrp + j] = zacc[j];
    __syncthreads();
    if (tid < 64) {
        float z = 0.0f;
#pragma unroll
        for (int p = 0; p < 32; p++) z += s_z[p][tid];
        g_zp[(bn * NCH + ch) * 64 + tid] = z;
    }

    // ---- fold: Sst[m][d] = C1[m][d] (w0,1) + C1[m+64][d] (w2,3) + C2[m][d] (w4-7)
    float* fold = (float*)s_tiles;   // 64 rows x 66 stride (reuse dynamic smem)

    if (wid == 2 || wid == 3) {
#pragma unroll
        for (int ai = 0; ai < 4; ai++)
#pragma unroll
            for (int nb = 0; nb < 4; nb++) {
                const int m = ai * 16 + g;
                const int d0 = dout + nb * 8 + 2 * tig;
                fold[m * 66 + d0]           = c[ai][nb][0];
                fold[m * 66 + d0 + 1]       = c[ai][nb][1];
                fold[(m + 8) * 66 + d0]     = c[ai][nb][2];
                fold[(m + 8) * 66 + d0 + 1] = c[ai][nb][3];
            }
    }
    __syncthreads();
    if (wid < 2) {
#pragma unroll
        for (int ai = 0; ai < 4; ai++)
#pragma unroll
            for (int nb = 0; nb < 4; nb++) {
                const int m = ai * 16 + g;
                const int d0 = dout + nb * 8 + 2 * tig;
                c[ai][nb][0] += fold[m * 66 + d0];
                c[ai][nb][1] += fold[m * 66 + d0 + 1];
                c[ai][nb][2] += fold[(m + 8) * 66 + d0];
                c[ai][nb][3] += fold[(m + 8) * 66 + d0 + 1];
            }
    }
    __syncthreads();
    if (wid >= 4) {
#pragma unroll
        for (int ai = 0; ai < 4; ai++)
#pragma unroll
            for (int nb = 0; nb < 2; nb++) {
                const int m = ai * 16 + g;
                const int d0 = dout + nb * 8 + 2 * tig;
                fold[m * 66 + d0]           = c[ai][nb][0];
                fold[m * 66 + d0 + 1]       = c[ai][nb][1];
                fold[(m + 8) * 66 + d0]     = c[ai][nb][2];
                fold[(m + 8) * 66 + d0 + 1] = c[ai][nb][3];
            }
    }
    __syncthreads();

    if (wid < 2) {
        float* so = g_part + ((size_t)bn * NCH + ch) * 4096;
#pragma unroll
        for (int ai = 0; ai < 4; ai++)
#pragma unroll
            for (int nb = 0; nb < 4; nb++) {
                const int m = ai * 16 + g;
                const int d0 = dout + nb * 8 + 2 * tig;
                float c0 = c[ai][nb][0] + fold[m * 66 + d0];
                float c1 = c[ai][nb][1] + fold[m * 66 + d0 + 1];
                float c2 = c[ai][nb][2] + fold[(m + 8) * 66 + d0];
                float c3 = c[ai][nb][3] + fold[(m + 8) * 66 + d0 + 1];
                *(float2*)(so + m * 64 + d0)       = make_float2(c0, c1);
                *(float2*)(so + (m + 8) * 64 + d0) = make_float2(c2, c3);
            }
    }

    // ---- arrival protocol: second CTA of this bn does the reduction ----
    __threadfence();
    __syncthreads();
    if (tid == 0) s_rank = atomicAdd(&g_cnt[bn], 1);
    __syncthreads();

    if (s_rank == 1) {
        __threadfence();   // acquire: other CTA's partials visible
        float* sst = (float*)s_tiles;   // reuse as 4096-float buffer

        const float* p0 = g_part + (size_t)bn * (NCH * 4096);
        for (int e = tid; e < 4096; e += 256) {
            const float s = p0[e] + p0[4096 + e];
            sst[e] = s;
            outS[(size_t)bn * 4096 + e] = s;
        }
        if (tid < 64) {
            const float z = g_zp[bn * 128 + tid] + g_zp[bn * 128 + 64 + tid];
            outZ[bn * 64 + tid] = z;
            const float q = elu1(query[bn * 64 + tid]);
            s_qs[tid] = q;
            s_red[tid] = q * z;
        }
        __syncthreads();
        if (tid == 0) {
            float s = 0.0f;
#pragma unroll
            for (int d = 0; d < 64; d++) s += s_red[d];
            s_sinv = 1.0f / (s + 1e-6f);
            g_cnt[bn] = 0;   // reset for next graph replay
        }
        __syncthreads();
        {
            const int m = tid >> 2;       // 0..63
            const int l4 = tid & 3;
            float v = 0.0f;
#pragma unroll
            for (int u = 0; u < 16; u++) {
                const int d = l4 * 16 + u;
                v += s_qs[d] * sst[m * 64 + d];
            }
            v += __shfl_xor_sync(0xFFFFFFFFu, v, 1);
            v += __shfl_xor_sync(0xFFFFFFFFu, v, 2);
            if (l4 == 0) outV[bn * 64 + m] = v * s_sinv;
        }
    }
}

// ---------------------------------------------------------------------------
extern "C" void kernel_launch(void* const* d_in, const int* in_sizes, int n_in,
                              void* d_out, int out_size)
{
    const float* query = (const float*)d_in[0];
    const float* key   = (const float*)d_in[1];
    const float* value = (const float*)d_in[2];
    const int*   mask  = (const int*)d_in[3];

    float* out  = (float*)d_out;
    float* outV = out;                        // [B,N,M]
    float* outS = out + V_ELEMS;              // [B,N,M,D]
    float* outZ = out + V_ELEMS + SST_ELEMS;  // [B,N,D]

    cudaFuncSetAttribute(rcla_hmma, cudaFuncAttributeMaxDynamicSharedMemorySize,
                         DYN_B);
    rcla_hmma<<<dim3(128, NCH), 256, DYN_B>>>(query, key, value, mask,
                                              outV, outS, outZ);
}

// round 17
// speedup vs baseline: 1.4964x; 1.3990x over previous
#include <cuda_runtime.h>
#include <cstdint>

// Shapes
#define Bq 8
#define Sq 8192
#define Nq 16
#define NCH 2                     // s-chunks (CTAs per bn)
#define SSUB (Sq / NCH)           // 4096
#define ST 32                     // s-rows per tile
#define NT2 (SSUB / ST)           // 128 tiles per CTA
#define RSTRIDE 272               // smem row stride bytes (136 bf16)
#define TILE_B (ST * RSTRIDE)     // 8704
#define BUF_B (2 * TILE_B)        // 17408 = V tile + K tile
#define V_ELEMS 8192
#define SST_ELEMS 524288

// Deterministic reduction scratch
__device__ float g_part[128 * NCH * 4096];   // 4 MB
__device__ float g_zp[128 * NCH * 64];

static __device__ __forceinline__ float elu1(float x) {
    return x > 0.0f ? x + 1.0f : __expf(x);
}
static __device__ __forceinline__ uint32_t smem_u32(const void* p) {
    uint32_t a;
    asm("{ .reg .u64 t; cvta.to.shared.u64 t, %1; cvt.u32.u64 %0, t; }" : "=r"(a) : "l"(p));
    return a;
}
static __device__ __forceinline__ uint32_t pk(float hi, float lo) {
    uint32_t r;
    asm("cvt.rn.bf16x2.f32 %0, %1, %2;" : "=r"(r) : "f"(hi), "f"(lo));
    return r;
}
static __device__ __forceinline__ float bf_lo(uint32_t p) {
    return __uint_as_float(p << 16);
}
static __device__ __forceinline__ float bf_up(uint32_t p) {
    return __uint_as_float(p & 0xFFFF0000u);
}
static __device__ __forceinline__ void ldsm4t(uint32_t* r, uint32_t a) {
    asm volatile("ldmatrix.sync.aligned.m8n8.x4.trans.shared.b16 {%0,%1,%2,%3}, [%4];"
                 : "=r"(r[0]), "=r"(r[1]), "=r"(r[2]), "=r"(r[3]) : "r"(a));
}
static __device__ __forceinline__ void mma16816(float* c, const uint32_t* a,
                                                uint32_t b0, uint32_t b1) {
    asm volatile(
        "mma.sync.aligned.m16n8k16.row.col.f32.bf16.bf16.f32 "
        "{%0,%1,%2,%3}, {%4,%5,%6,%7}, {%8,%9}, {%0,%1,%2,%3};"
        : "+f"(c[0]), "+f"(c[1]), "+f"(c[2]), "+f"(c[3])
        : "r"(a[0]), "r"(a[1]), "r"(a[2]), "r"(a[3]), "r"(b0), "r"(b1));
}
static __device__ __forceinline__ void sts128(uint32_t a, uint32_t x, uint32_t y,
                                              uint32_t z, uint32_t w) {
    asm volatile("st.shared.v4.b32 [%0], {%1,%2,%3,%4};"
                 :: "r"(a), "r"(x), "r"(y), "r"(z), "r"(w) : "memory");
}

// ---------------------------------------------------------------------------
// Phase 1: per (bn, chunk) partial Sst (64x64 fp32) + partial Z.
// 3-quadrant split: warps 0-3: C1=[Vh;Vl]x Kh (64x32 each, 16 HMMA);
//                   warps 4-7: C2= Vh x Kl   (64x16 each,  8 HMMA).
// ---------------------------------------------------------------------------
__global__ void __launch_bounds__(256, 2) rcla_hmma(
    const float* __restrict__ key,     // [B,S,N,64]
    const float* __restrict__ value,   // [B,S,N,64]
    const int*   __restrict__ kmask)   // [B,S] nonzero = masked
{
    __shared__ __align__(16) unsigned char s_tiles[2 * BUF_B];  // 34816 B
    __shared__ float s_z[ST][64];                               // 8 KB

    const int tid = threadIdx.x;
    const int wid = tid >> 5;
    const int lid = tid & 31;
    const int bn = blockIdx.x;
    const int ch = blockIdx.y;
    const int b = bn >> 4;
    const int n = bn & 15;

    const uint32_t sb = smem_u32(s_tiles);

    // ---- staging mapping ----
    const int s_loc = tid >> 3;            // 0..31
    const int dgrp = (tid & 7) * 8;        // 0..56
    const uint32_t st_off = (uint32_t)s_loc * RSTRIDE + dgrp * 2;

    const int sbase = ch * SSUB + s_loc;
    const float* kg = key   + (((size_t)b * Sq + sbase) * Nq + n) * 64 + dgrp;
    const float* vg = value + (((size_t)b * Sq + sbase) * Nq + n) * 64 + dgrp;
    const int*   mg = kmask + b * Sq + sbase;
    const size_t GSTR = (size_t)ST * Nq * 64;

    // ---- mma mapping ----
    const bool isC1 = wid < 4;
    const int mbase = isC1 ? ((wid & 2) ? 64 : 0) : 0;          // A rows
    const int dsm   = isC1 ? ((wid & 1) * 32) : (64 + (wid & 3) * 16);  // B smem col
    const int dout  = isC1 ? ((wid & 1) * 32) : ((wid & 3) * 16);       // output d
    const int g = lid >> 2;
    const int tig = lid & 3;

    const uint32_t offA = (uint32_t)((lid & 7) + ((lid & 16) ? 8 : 0)) * RSTRIDE
                        + (uint32_t)(mbase + ((lid & 8) ? 8 : 0)) * 2;
    const uint32_t offB = (uint32_t)((lid & 7) + ((lid & 8) ? 8 : 0)) * RSTRIDE
                        + (uint32_t)(dsm + ((lid & 16) ? 8 : 0)) * 2;

    float c[4][4][4];
#pragma unroll
    for (int i = 0; i < 4; i++)
#pragma unroll
        for (int j = 0; j < 4; j++)
#pragma unroll
            for (int r = 0; r < 4; r++) c[i][j][r] = 0.0f;
    float zacc[8];
#pragma unroll
    for (int j = 0; j < 8; j++) zacc[j] = 0.0f;

    // prefetch tile 0
    float4 k0 = *(const float4*)kg;
    float4 k1 = *(const float4*)(kg + 4);
    float4 v0 = *(const float4*)vg;
    float4 v1 = *(const float4*)(vg + 4);
    int mk = *mg;

    for (int it = 0; it < NT2; it++) {
        const uint32_t vt = sb + (it & 1) * BUF_B;
        const uint32_t kt = vt + TILE_B;

        // ---- stage K (mask + elu + split) ----
        {
            const float mm = mk ? 0.0f : 1.0f;
            float f0 = mm * elu1(k0.x), f1 = mm * elu1(k0.y);
            float f2 = mm * elu1(k0.z), f3 = mm * elu1(k0.w);
            float f4 = mm * elu1(k1.x), f5 = mm * elu1(k1.y);
            float f6 = mm * elu1(k1.z), f7 = mm * elu1(k1.w);
            zacc[0] += f0; zacc[1] += f1; zacc[2] += f2; zacc[3] += f3;
            zacc[4] += f4; zacc[5] += f5; zacc[6] += f6; zacc[7] += f7;
            const uint32_t h01 = pk(f1, f0), h23 = pk(f3, f2);
            const uint32_t h45 = pk(f5, f4), h67 = pk(f7, f6);
            sts128(kt + st_off, h01, h23, h45, h67);
            const uint32_t l01 = pk(f1 - bf_up(h01), f0 - bf_lo(h01));
            const uint32_t l23 = pk(f3 - bf_up(h23), f2 - bf_lo(h23));
            const uint32_t l45 = pk(f5 - bf_up(h45), f4 - bf_lo(h45));
            const uint32_t l67 = pk(f7 - bf_up(h67), f6 - bf_lo(h67));
            sts128(kt + st_off + 128, l01, l23, l45, l67);
        }
        // ---- stage V (split) ----
        {
            const float f0 = v0.x, f1 = v0.y, f2 = v0.z, f3 = v0.w;
            const float f4 = v1.x, f5 = v1.y, f6 = v1.z, f7 = v1.w;
            const uint32_t h01 = pk(f1, f0), h23 = pk(f3, f2);
            const uint32_t h45 = pk(f5, f4), h67 = pk(f7, f6);
            sts128(vt + st_off, h01, h23, h45, h67);
            const uint32_t l01 = pk(f1 - bf_up(h01), f0 - bf_lo(h01));
            const uint32_t l23 = pk(f3 - bf_up(h23), f2 - bf_lo(h23));
            const uint32_t l45 = pk(f5 - bf_up(h45), f4 - bf_lo(h45));
            const uint32_t l67 = pk(f7 - bf_up(h67), f6 - bf_lo(h67));
            sts128(vt + st_off + 128, l01, l23, l45, l67);
        }

        // ---- prefetch next tile ----
        if (it + 1 < NT2) {
            kg += GSTR; vg += GSTR; mg += ST;
            k0 = *(const float4*)kg;
            k1 = *(const float4*)(kg + 4);
            v0 = *(const float4*)vg;
            v1 = *(const float4*)(vg + 4);
            mk = *mg;
        }

        __syncthreads();   // stage visible; also fences reads of this buf @ it-2

        // ---- compute: 2 k-steps of 16 ----
#pragma unroll
        for (int ks = 0; ks < 2; ks++) {
            const uint32_t rowoff = (uint32_t)ks * 16 * RSTRIDE;
            uint32_t a[4][4];
#pragma unroll
            for (int ai = 0; ai < 4; ai++)
                ldsm4t(a[ai], vt + rowoff + offA + ai * 32);
            if (isC1) {
                uint32_t bb[2][4];
#pragma unroll
                for (int bj = 0; bj < 2; bj++)
                    ldsm4t(bb[bj], kt + rowoff + offB + bj * 32);
#pragma unroll
                for (int ai = 0; ai < 4; ai++)
#pragma unroll
                    for (int nb = 0; nb < 4; nb++)
                        mma16816(c[ai][nb], a[ai],
                                 bb[nb >> 1][(nb & 1) * 2],
                                 bb[nb >> 1][(nb & 1) * 2 + 1]);
            } else {
                uint32_t bb[4];
                ldsm4t(bb, kt + rowoff + offB);
#pragma unroll
                for (int ai = 0; ai < 4; ai++) {
                    mma16816(c[ai][0], a[ai], bb[0], bb[1]);
                    mma16816(c[ai][1], a[ai], bb[2], bb[3]);
                }
            }
        }
        // no trailing sync: next iteration writes the other buffer
    }

    // ---- partial Z ----
#pragma unroll
    for (int j = 0; j < 8; j++) s_z[s_loc][dgrp + j] = zacc[j];
    __syncthreads();
    if (tid < 64) {
        float z = 0.0f;
#pragma unroll
        for (int p = 0; p < ST; p++) z += s_z[p][tid];
        g_zp[(bn * NCH + ch) * 64 + tid] = z;
    }

    // ---- fold: Sst[m][d] = C1[m][d] (w0,1) + C1[m+64][d] (w2,3) + C2[m][d] (w4-7)
    float* fold = (float*)s_tiles;   // 64 rows x 66 stride

    if (wid == 2 || wid == 3) {
#pragma unroll
        for (int ai = 0; ai < 4; ai++)
#pragma unroll
            for (int nb = 0; nb < 4; nb++) {
                const int m = ai * 16 + g;
                const int d0 = dout + nb * 8 + 2 * tig;
                fold[m * 66 + d0]           = c[ai][nb][0];
                fold[m * 66 + d0 + 1]       = c[ai][nb][1];
                fold[(m + 8) * 66 + d0]     = c[ai][nb][2];
                fold[(m + 8) * 66 + d0 + 1] = c[ai][nb][3];
            }
    }
    __syncthreads();
    if (wid < 2) {
#pragma unroll
        for (int ai = 0; ai < 4; ai++)
#pragma unroll
            for (int nb = 0; nb < 4; nb++) {
                const int m = ai * 16 + g;
                const int d0 = dout + nb * 8 + 2 * tig;
                c[ai][nb][0] += fold[m * 66 + d0];
                c[ai][nb][1] += fold[m * 66 + d0 + 1];
                c[ai][nb][2] += fold[(m + 8) * 66 + d0];
                c[ai][nb][3] += fold[(m + 8) * 66 + d0 + 1];
            }
    }
    __syncthreads();
    if (wid >= 4) {
#pragma unroll
        for (int ai = 0; ai < 4; ai++)
#pragma unroll
            for (int nb = 0; nb < 2; nb++) {
                const int m = ai * 16 + g;
                const int d0 = dout + nb * 8 + 2 * tig;
                fold[m * 66 + d0]           = c[ai][nb][0];
                fold[m * 66 + d0 + 1]       = c[ai][nb][1];
                fold[(m + 8) * 66 + d0]     = c[ai][nb][2];
                fold[(m + 8) * 66 + d0 + 1] = c[ai][nb][3];
            }
    }
    __syncthreads();

    // ---- warps 0,1: final add + write partial Sst ----
    if (wid < 2) {
        float* so = g_part + ((size_t)bn * NCH + ch) * 4096;
#pragma unroll
        for (int ai = 0; ai < 4; ai++)
#pragma unroll
            for (int nb = 0; nb < 4; nb++) {
                const int m = ai * 16 + g;
                const int d0 = dout + nb * 8 + 2 * tig;
                float c0 = c[ai][nb][0] + fold[m * 66 + d0];
                float c1 = c[ai][nb][1] + fold[m * 66 + d0 + 1];
                float c2 = c[ai][nb][2] + fold[(m + 8) * 66 + d0];
                float c3 = c[ai][nb][3] + fold[(m + 8) * 66 + d0 + 1];
                *(float2*)(so + m * 64 + d0)       = make_float2(c0, c1);
                *(float2*)(so + (m + 8) * 64 + d0) = make_float2(c2, c3);
            }
    }
}

// ---------------------------------------------------------------------------
// Phase 2: deterministic 2-way reduction + epilogue, parallelized 4x.
// grid 512: block = (bn, quarter). Each block: 16 Sst rows + V rows + sinv.
// ---------------------------------------------------------------------------
__global__ void __launch_bounds__(256) rcla_reduce(
    const float* __restrict__ query,  // [B,N,64]
    float* __restrict__ outV,         // [B,N,64]
    float* __restrict__ outS,         // [B,N,64,64]
    float* __restrict__ outZ)         // [B,N,64]
{
    const int bx = blockIdx.x;
    const int bn = bx >> 2;
    const int qr = bx & 3;
    const int tid = threadIdx.x;

    __shared__ float sst[1024];
    __shared__ float qs[64];
    __shared__ float red[64];
    __shared__ float sinv;

    // Z (full), q, sinv inputs
    if (tid < 64) {
        const float z = g_zp[bn * 128 + tid] + g_zp[bn * 128 + 64 + tid];
        if (qr == 0) outZ[bn * 64 + tid] = z;
        const float q = elu1(query[bn * 64 + tid]);
        qs[tid] = q;
        red[tid] = q * z;
    }
    __syncthreads();
    if (tid == 0) {
        float s = 0.0f;
#pragma unroll
        for (int d = 0; d < 64; d++) s += red[d];
        sinv = 1.0f / (s + 1e-6f);
    }

    // Sst quarter: rows [16*qr, 16*qr+16)
    const float* p0 = g_part + (size_t)bn * (NCH * 4096) + qr * 1024;
    for (int e = tid; e < 1024; e += 256) {
        const float s = p0[e] + p0[4096 + e];
        sst[e] = s;
        outS[(size_t)bn * 4096 + qr * 1024 + e] = s;
    }
    __syncthreads();

    // V: one 16-lane group per row
    {
        const int r = tid >> 4;        // 0..15
        const int l = tid & 15;
        float v = 0.0f;
#pragma unroll
        for (int u = 0; u < 4; u++) {
            const int d = l + 16 * u;
            v += qs[d] * sst[r * 64 + d];
        }
        v += __shfl_xor_sync(0xFFFFFFFFu, v, 1);
        v += __shfl_xor_sync(0xFFFFFFFFu, v, 2);
        v += __shfl_xor_sync(0xFFFFFFFFu, v, 4);
        v += __shfl_xor_sync(0xFFFFFFFFu, v, 8);
        if (l == 0) outV[bn * 64 + qr * 16 + r] = v * sinv;
    }
}

// ---------------------------------------------------------------------------
extern "C" void kernel_launch(void* const* d_in, const int* in_sizes, int n_in,
                              void* d_out, int out_size)
{
    const float* query = (const float*)d_in[0];
    const float* key   = (const float*)d_in[1];
    const float* value = (const float*)d_in[2];
    const int*   mask  = (const int*)d_in[3];

    float* out  = (float*)d_out;
    float* outV = out;                        // [B,N,M]
    float* outS = out + V_ELEMS;              // [B,N,M,D]
    float* outZ = out + V_ELEMS + SST_ELEMS;  // [B,N,D]

    rcla_hmma<<<dim3(128, NCH), 256>>>(key, value, mask);
    rcla_reduce<<<512, 256>>>(query, outV, outS, outZ);
}